// round 16
// baseline (speedup 1.0000x reference)
#include <cuda_runtime.h>
#include <cuda_fp16.h>
#include <cuda_bf16.h>
#include <cstdint>

#define NN 40000
#define EE 640000
#define DD 128
#define LL 5
#define NTILES 625          // NN / 64 (64-row GEMM tiles, exact)

// ---------------- device scratch (static, no allocation) ----------------
__device__ float g_z0[NN * DD];   // agg output / gemm2 output
__device__ float g_y1[NN * DD];   // gemm1 output
__device__ __half g_hh[NN * DD];  // fp16 shadow of h (gather source)
__device__ int   g_rowptr[NN + 1];
__device__ int   g_cursor[NN];
__device__ int   g_packed[EE];    // (src<<5) | (attr*32)<<21, grouped by dst
__device__ int   g_bflag[40];
__device__ int   g_bpre[40];
__device__ int   g_bar;
__device__ int   g_ctr[2];        // work-stealing counters (gemm1, gemm2)
__device__ float g_sum1[DD], g_sq1[DD];   // stats of gemm1 output (BN1)
__device__ float g_sum2[DD], g_sq2[DD];   // stats of gemm2 output (BN2)
__device__ uint4 g_wth4[10 * 2048];
__device__ uint4 g_wtl4[10 * 2048];

// ---------------- helpers ----------------
__device__ __forceinline__ uint32_t smem_u32(const void* p) {
    uint32_t a;
    asm("{ .reg .u64 t; cvta.to.shared.u64 t, %1; cvt.u32.u64 %0, t; }" : "=r"(a) : "l"(p));
    return a;
}
__device__ __forceinline__ void cpasync16(uint32_t dst, const void* src) {
    asm volatile("cp.async.cg.shared.global [%0], [%1], 16;" :: "r"(dst), "l"(src) : "memory");
}
__device__ __forceinline__ void ldsm4(uint32_t a, uint32_t& r0, uint32_t& r1,
                                      uint32_t& r2, uint32_t& r3) {
    asm volatile("ldmatrix.sync.aligned.m8n8.x4.shared.b16 {%0,%1,%2,%3}, [%4];"
                 : "=r"(r0), "=r"(r1), "=r"(r2), "=r"(r3) : "r"(a));
}
__device__ __forceinline__ void mma16816(float* c, const uint32_t* a, uint32_t b0, uint32_t b1) {
    asm volatile(
        "mma.sync.aligned.m16n8k16.row.col.f32.bf16.bf16.f32 "
        "{%0,%1,%2,%3}, {%4,%5,%6,%7}, {%8,%9}, {%0,%1,%2,%3};"
        : "+f"(c[0]), "+f"(c[1]), "+f"(c[2]), "+f"(c[3])
        : "r"(a[0]), "r"(a[1]), "r"(a[2]), "r"(a[3]), "r"(b0), "r"(b1));
}
__device__ __forceinline__ void split2(float a, float b, uint32_t& hi, uint32_t& lo) {
    __nv_bfloat16 ha = __float2bfloat16_rn(a), hb = __float2bfloat16_rn(b);
    float ra = a - __bfloat162float(ha), rb = b - __bfloat162float(hb);
    __nv_bfloat162 ph = __halves2bfloat162(ha, hb);
    __nv_bfloat162 pl = __halves2bfloat162(__float2bfloat16_rn(ra), __float2bfloat16_rn(rb));
    hi = *(uint32_t*)&ph;
    lo = *(uint32_t*)&pl;
}
__device__ __forceinline__ uint2 f2h4(float4 v) {
    __half2 lo = __floats2half2_rn(v.x, v.y);
    __half2 hi = __floats2half2_rn(v.z, v.w);
    uint2 r;
    r.x = *(unsigned*)&lo;
    r.y = *(unsigned*)&hi;
    return r;
}
// message = relu(h_src + bond) for a uint4 (8 halves)
__device__ __forceinline__ void msg4(uint4 r, uint4 e, __half2* m, __half2 z2) {
    m[0] = __hmax2(__hadd2(*(__half2*)&r.x, *(__half2*)&e.x), z2);
    m[1] = __hmax2(__hadd2(*(__half2*)&r.y, *(__half2*)&e.y), z2);
    m[2] = __hmax2(__hadd2(*(__half2*)&r.z, *(__half2*)&e.z), z2);
    m[3] = __hmax2(__hadd2(*(__half2*)&r.w, *(__half2*)&e.w), z2);
}
__device__ __forceinline__ void flushh(__half2 c0, __half2 c1, __half2 c2, __half2 c3,
                                       float2& a0, float2& a1, float2& a2, float2& a3) {
    float2 f0 = __half22float2(c0), f1 = __half22float2(c1);
    float2 f2 = __half22float2(c2), f3 = __half22float2(c3);
    a0.x += f0.x; a0.y += f0.y;
    a1.x += f1.x; a1.y += f1.y;
    a2.x += f2.x; a2.y += f2.y;
    a3.x += f3.x; a3.y += f3.y;
}

// ---------------- embed + wconv + per-replay zeroing + fp16 shadow ----------------
__global__ void embed_kernel(float4* __restrict__ h4,
                             const int* __restrict__ x_ids,
                             const float4* __restrict__ atom4,
                             const float* __restrict__ W1,
                             const float* __restrict__ W2) {
    int blk = blockIdx.x;
    if (blk < 5000) {
        int i = blk * 256 + threadIdx.x;
        if (i < NN) g_cursor[i] = 0;
        if (i < 40) { g_bflag[i] = 0; g_bpre[i] = 0; }
        if (i < 2) g_ctr[i] = 0;
        if (i == 42) g_bar = 0;
        int n = i >> 5, c = i & 31;
        float4 v = __ldg(&atom4[x_ids[n] * 32 + c]);
        h4[i] = v;
        ((uint2*)g_hh)[i] = f2h4(v);
    } else {
        int i = (blk - 5000) * 256 + threadIdx.x;   // 0..163839
        int which = i >> 14;
        int j = i & 16383;
        int n = j >> 7, k = j & 127;
        const float* W = ((which & 1) ? W2 : W1) + (which >> 1) * DD * DD;
        float v = __ldg(&W[k * DD + n]);
        __nv_bfloat16 h = __float2bfloat16_rn(v);
        float r = v - __bfloat162float(h);
        ((__nv_bfloat16*)g_wth4)[i] = h;
        ((__nv_bfloat16*)g_wtl4)[i] = __float2bfloat16_rn(r);
    }
}

// ---------------- CSR build: hist + scan (lookback) + scatter, one kernel ----------------
__global__ void __launch_bounds__(1024) scan_scatter_kernel(const int* __restrict__ ei,
                                                            const int* __restrict__ eattr) {
    __shared__ int wsum[32];
    __shared__ int s_boff;
    int tid = threadIdx.x, lane = tid & 31, wid = tid >> 5;
    int b = blockIdx.x;

    for (int e = b * 16000 + tid; e < (b + 1) * 16000; e += 1024)
        atomicAdd(&g_cursor[ei[EE + e]], 1);
    __threadfence();
    __syncthreads();
    if (tid == 0) {
        atomicAdd(&g_bar, 1);
        while (((volatile int*)&g_bar)[0] < 40) { }
    }
    __syncthreads();

    int i = b * 1024 + tid;
    int v = (i < NN) ? g_cursor[i] : 0;
    int x = v;
    #pragma unroll
    for (int o = 1; o < 32; o <<= 1) { int t = __shfl_up_sync(~0u, x, o); if (lane >= o) x += t; }
    if (lane == 31) wsum[wid] = x;
    __syncthreads();
    if (wid == 0) {
        int y = wsum[lane];
        #pragma unroll
        for (int o = 1; o < 32; o <<= 1) { int t = __shfl_up_sync(~0u, y, o); if (lane >= o) y += t; }
        wsum[lane] = y;
    }
    __syncthreads();
    int incl = (wid ? wsum[wid - 1] : 0) + x;
    if (tid == 0) {
        int total = wsum[31];
        int p = 0;
        if (b > 0) {
            while (((volatile int*)g_bflag)[b - 1] == 0) { }
            p = ((volatile int*)g_bpre)[b - 1];
        }
        g_bpre[b] = p + total;
        __threadfence();
        ((volatile int*)g_bflag)[b] = 1;
        s_boff = p;
    }
    __syncthreads();
    int boff = s_boff;
    if (i < NN) {
        g_rowptr[i + 1] = boff + incl;
        g_cursor[i] = boff + incl - v;
    }
    if (i == 0) g_rowptr[0] = 0;
    __threadfence();
    __syncthreads();
    if (tid == 0) {
        atomicAdd(&g_bar, 1);
        while (((volatile int*)&g_bar)[0] < 80) { }
    }
    __syncthreads();

    for (int e = b * 16000 + tid; e < (b + 1) * 16000; e += 1024) {
        int d = ei[EE + e];
        int p = atomicAdd(&g_cursor[d], 1);
        g_packed[p] = (ei[e] << 5) | ((eattr[e] << 5) << 21);
    }
}

// ---------------- edge aggregation (half-warp pairing) ----------------
__global__ void __launch_bounds__(256) agg_kernel(const float4* __restrict__ h4,
                                                  const float* __restrict__ bond_emb,
                                                  const float* __restrict__ eps, int l) {
    __shared__ uint4 sbe4[4 * 16];
    int tid = threadIdx.x;
    if (blockIdx.x == 0 && tid < 128) {
        g_sum1[tid] = 0.f; g_sq1[tid] = 0.f;
        g_sum2[tid] = 0.f; g_sq2[tid] = 0.f;
        if (tid < 2) g_ctr[tid] = 0;
    }
    if (tid < 64) {
        float4 a = __ldg((const float4*)(bond_emb + l * 512) + tid * 2);
        float4 b = __ldg((const float4*)(bond_emb + l * 512) + tid * 2 + 1);
        uint2 pa = f2h4(a), pb = f2h4(b);
        sbe4[tid] = make_uint4(pa.x, pa.y, pb.x, pb.y);
    }
    __syncthreads();
    int lane = tid & 31, hf = lane >> 4, li = lane & 15;
    int v = blockIdx.x * 8 + (tid >> 5);
    float ep = 1.0f + __ldg(&eps[l]);
    const uint4* hh4 = (const uint4*)g_hh;
    const __half2 z2 = __float2half2_rn(0.f);

    float2 a0, a1, a2, a3;
    if (hf == 0) {
        float4 h0 = __ldg(&h4[v * 32 + li * 2]);
        float4 h1 = __ldg(&h4[v * 32 + li * 2 + 1]);
        a0 = make_float2(h0.x * ep, h0.y * ep);
        a1 = make_float2(h0.z * ep, h0.w * ep);
        a2 = make_float2(h1.x * ep, h1.y * ep);
        a3 = make_float2(h1.z * ep, h1.w * ep);
    } else {
        a0 = a1 = a2 = a3 = make_float2(0.f, 0.f);
    }

    int start = g_rowptr[v], end = g_rowptr[v + 1];
    for (int base = start; base < end; base += 32) {
        int nl = min(32, end - base);
        int pk = (base + lane < end) ? g_packed[base + lane] : 0;
        for (int j = 0; j < nl; j += 4) {
            int eA = j + hf, eB = j + 2 + hf;
            int pA = __shfl_sync(~0u, pk, eA);
            int pB = __shfl_sync(~0u, pk, eB);
            bool vA = eA < nl, vB = eB < nl;
            uint4 rA = __ldg(&hh4[((pA & 0x1FFFFF) >> 1) + li]);
            uint4 eAv = sbe4[(((unsigned)pA >> 21) >> 1) + li];
            uint4 rB = __ldg(&hh4[((pB & 0x1FFFFF) >> 1) + li]);
            uint4 eBv = sbe4[(((unsigned)pB >> 21) >> 1) + li];
            __half2 mA[4], mB[4];
            msg4(rA, eAv, mA, z2);
            msg4(rB, eBv, mB, z2);
            if (vB) {
                flushh(__hadd2(mA[0], mB[0]), __hadd2(mA[1], mB[1]),
                       __hadd2(mA[2], mB[2]), __hadd2(mA[3], mB[3]), a0, a1, a2, a3);
            } else if (vA) {
                flushh(mA[0], mA[1], mA[2], mA[3], a0, a1, a2, a3);
            }
        }
    }
    a0.x += __shfl_xor_sync(~0u, a0.x, 16);
    a0.y += __shfl_xor_sync(~0u, a0.y, 16);
    a1.x += __shfl_xor_sync(~0u, a1.x, 16);
    a1.y += __shfl_xor_sync(~0u, a1.y, 16);
    a2.x += __shfl_xor_sync(~0u, a2.x, 16);
    a2.y += __shfl_xor_sync(~0u, a2.y, 16);
    a3.x += __shfl_xor_sync(~0u, a3.x, 16);
    a3.y += __shfl_xor_sync(~0u, a3.y, 16);
    if (hf == 0) {
        *((float4*)g_z0 + v * 32 + li * 2)     = make_float4(a0.x, a0.y, a1.x, a1.y);
        *((float4*)g_z0 + v * 32 + li * 2 + 1) = make_float4(a2.x, a2.y, a3.x, a3.y);
    }
}

// ---------------- tensor-core GEMM (mma.sync bf16, 3-term split) ----------------
// CTA tile 64x128, 8 warps 2m x 4n, warp tile m32 x n32; cp.async B staging;
// A register prefetch across tiles; claim-ahead; register stats.
#define SM_AH    0
#define SM_AL    17408
#define SM_BH    34816
#define SM_BL    69632
#define SM_SUM   104448
#define SM_SQ    104960
#define SM_SCALE 105472
#define SM_SHIFT 105984
#define SM_TILE  106496
#define SMEM_GEMM 106512

template <bool TRANS>
__global__ void __launch_bounds__(256, 2) gemm_kernel(int which,
                                                      const float* __restrict__ bias,
                                                      const float* __restrict__ gamma,
                                                      const float* __restrict__ beta,
                                                      int ctr_idx) {
    extern __shared__ char smem[];
    uint32_t sb = smem_u32(smem);
    float* s_sum   = (float*)(smem + SM_SUM);
    float* s_sq    = (float*)(smem + SM_SQ);
    float* s_scale = (float*)(smem + SM_SCALE);
    float* s_shift = (float*)(smem + SM_SHIFT);
    int*   s_tile  = (int*)(smem + SM_TILE);
    const float* A = TRANS ? g_y1 : g_z0;
    float* C       = TRANS ? g_z0 : g_y1;

    int tid = threadIdx.x, lane = tid & 31, wid = tid >> 5;
    {   // B staging via cp.async (overlapped with everything below)
        const uint4* srcH = g_wth4 + which * 2048;
        const uint4* srcL = g_wtl4 + which * 2048;
        #pragma unroll
        for (int it = 0; it < 8; it++) {
            int s = it * 256 + tid;
            int row = s >> 4, ch = s & 15;
            cpasync16(sb + SM_BH + row * 272 + ch * 16, srcH + row * 16 + ch);
            cpasync16(sb + SM_BL + row * 272 + ch * 16, srcL + row * 16 + ch);
        }
        asm volatile("cp.async.commit_group;" ::: "memory");
    }
    if (tid < 128) {
        s_sum[tid] = 0.f; s_sq[tid] = 0.f;
        if (TRANS) {
            const float invN = 1.0f / (float)NN;
            float m   = g_sum1[tid] * invN;
            float var = g_sq1[tid] * invN - m * m;
            float sc  = __ldg(&gamma[tid]) * rsqrtf(var + 1e-5f);
            s_scale[tid] = sc;
            s_shift[tid] = __ldg(&beta[tid]) - m * sc;
        }
    }

    int mrow = (wid & 1) * 32;
    int ncol = (wid >> 1) * 32;
    int gm = lane & 7, gh = (lane >> 3) & 1, gk = lane >> 4;
    uint32_t aA0 = sb + (mrow + gm + gh * 8) * 272 + gk * 16;
    uint32_t aB0 = sb + (ncol + gm + gh * 8) * 272 + gk * 16;
    int ar = tid >> 5, ac4 = tid & 31;

    float st_sx0[4] = {}, st_sx1[4] = {}, st_sq0[4] = {}, st_sq1[4] = {};

    // prologue: claim first tile + prefetch its A into registers
    if (tid == 0) *s_tile = atomicAdd(&g_ctr[ctr_idx], 1);
    __syncthreads();
    int t = *s_tile;
    float4 vA[8];
    if (t < NTILES) {
        #pragma unroll
        for (int i = 0; i < 8; i++)
            vA[i] = __ldg((const float4*)(A + (t * 64 + ar + i * 8) * DD) + ac4);
    }

    while (t < NTILES) {
        int rowblk = t * 64;
        {   // transform + bf16 split + store prefetched A
            float4 sc, sh;
            if (TRANS) {
                sc = *(const float4*)(s_scale + ac4 * 4);
                sh = *(const float4*)(s_shift + ac4 * 4);
            }
            #pragma unroll
            for (int i = 0; i < 8; i++) {
                float4 v = vA[i];
                if (TRANS) {
                    v.x = fmaxf(fmaf(v.x, sc.x, sh.x), 0.f);
                    v.y = fmaxf(fmaf(v.y, sc.y, sh.y), 0.f);
                    v.z = fmaxf(fmaf(v.z, sc.z, sh.z), 0.f);
                    v.w = fmaxf(fmaf(v.w, sc.w, sh.w), 0.f);
                }
                uint32_t h0, l0, h1, l1;
                split2(v.x, v.y, h0, l0);
                split2(v.z, v.w, h1, l1);
                char* p = smem + (ar + i * 8) * 272 + ac4 * 8;
                *(uint2*)(p + SM_AH) = make_uint2(h0, h1);
                *(uint2*)(p + SM_AL) = make_uint2(l0, l1);
            }
        }
        if (tid == 0) *s_tile = atomicAdd(&g_ctr[ctr_idx], 1);   // claim-ahead
        asm volatile("cp.async.wait_group 0;" ::: "memory");     // B ready (no-op after iter 1)
        __syncthreads();
        int tn = *s_tile;

        float c[2][4][4];
        #pragma unroll
        for (int mb = 0; mb < 2; mb++)
            #pragma unroll
            for (int i = 0; i < 4; i++)
                #pragma unroll
                for (int j = 0; j < 4; j++) c[mb][i][j] = 0.f;

        #pragma unroll
        for (int ks = 0; ks < 8; ks++) {
            uint32_t off = ks * 32;
            uint32_t ah[8], al[8], bh[8], bl[8];
            ldsm4(aA0 + SM_AH + off,            ah[0], ah[1], ah[2], ah[3]);
            ldsm4(aA0 + SM_AH + 16 * 272 + off, ah[4], ah[5], ah[6], ah[7]);
            ldsm4(aA0 + SM_AL + off,            al[0], al[1], al[2], al[3]);
            ldsm4(aA0 + SM_AL + 16 * 272 + off, al[4], al[5], al[6], al[7]);
            ldsm4(aB0 + SM_BH + off,            bh[0], bh[1], bh[2], bh[3]);
            ldsm4(aB0 + SM_BH + 16 * 272 + off, bh[4], bh[5], bh[6], bh[7]);
            ldsm4(aB0 + SM_BL + off,            bl[0], bl[1], bl[2], bl[3]);
            ldsm4(aB0 + SM_BL + 16 * 272 + off, bl[4], bl[5], bl[6], bl[7]);
            #pragma unroll
            for (int mb = 0; mb < 2; mb++) {
                #pragma unroll
                for (int ng = 0; ng < 4; ng++) {
                    int bi = (ng >> 1) * 4 + (ng & 1);
                    mma16816(c[mb][ng], ah + mb * 4, bh[bi], bh[bi + 2]);
                    mma16816(c[mb][ng], al + mb * 4, bh[bi], bh[bi + 2]);
                    mma16816(c[mb][ng], ah + mb * 4, bl[bi], bl[bi + 2]);
                }
            }
        }

        // prefetch next tile's A (covered by epilogue stores)
        if (tn < NTILES) {
            #pragma unroll
            for (int i = 0; i < 8; i++)
                vA[i] = __ldg((const float4*)(A + (tn * 64 + ar + i * 8) * DD) + ac4);
        }

        // epilogue: bias, store C; stats into registers only
        #pragma unroll
        for (int ng = 0; ng < 4; ng++) {
            int col0 = ncol + ng * 8 + 2 * (lane & 3);
            float bx = __ldg(&bias[col0]), by = __ldg(&bias[col0 + 1]);
            #pragma unroll
            for (int mb = 0; mb < 2; mb++) {
                int r0g = rowblk + mrow + mb * 16 + (lane >> 2);
                float x0 = c[mb][ng][0] + bx, x1 = c[mb][ng][1] + by;
                float x2 = c[mb][ng][2] + bx, x3 = c[mb][ng][3] + by;
                *(float2*)(C + r0g * DD + col0)       = make_float2(x0, x1);
                *(float2*)(C + (r0g + 8) * DD + col0) = make_float2(x2, x3);
                st_sx0[ng] += x0 + x2; st_sq0[ng] += x0 * x0 + x2 * x2;
                st_sx1[ng] += x1 + x3; st_sq1[ng] += x1 * x1 + x3 * x3;
            }
        }
        __syncthreads();
        t = tn;
    }

    // final stats reduction (once per kernel)
    #pragma unroll
    for (int ng = 0; ng < 4; ng++) {
        float sx0 = st_sx0[ng], sq0 = st_sq0[ng], sx1 = st_sx1[ng], sq1 = st_sq1[ng];
        #pragma unroll
        for (int d = 4; d < 32; d <<= 1) {
            sx0 += __shfl_xor_sync(~0u, sx0, d);
            sq0 += __shfl_xor_sync(~0u, sq0, d);
            sx1 += __shfl_xor_sync(~0u, sx1, d);
            sq1 += __shfl_xor_sync(~0u, sq1, d);
        }
        if ((lane >> 2) == 0) {
            int col0 = ncol + ng * 8 + 2 * (lane & 3);
            atomicAdd(&s_sum[col0], sx0);
            atomicAdd(&s_sum[col0 + 1], sx1);
            atomicAdd(&s_sq[col0], sq0);
            atomicAdd(&s_sq[col0 + 1], sq1);
        }
    }
    __syncthreads();
    if (tid < 128) {
        if (TRANS) {
            atomicAdd(&g_sum2[tid], s_sum[tid]);
            atomicAdd(&g_sq2[tid],  s_sq[tid]);
        } else {
            atomicAdd(&g_sum1[tid], s_sum[tid]);
            atomicAdd(&g_sq1[tid],  s_sq[tid]);
        }
    }
}

// ---------------- BN2 + (relu) + residual + fp16 shadow refresh ----------------
__global__ void residual_kernel(float4* __restrict__ h4,
                                const float* __restrict__ gamma,
                                const float* __restrict__ beta,
                                int do_relu) {
    __shared__ float s_scale[128], s_shift[128];
    int tid = threadIdx.x;
    if (tid < 128) {
        const float invN = 1.0f / (float)NN;
        float m   = g_sum2[tid] * invN;
        float var = g_sq2[tid] * invN - m * m;
        float sc  = __ldg(&gamma[tid]) * rsqrtf(var + 1e-5f);
        s_scale[tid] = sc;
        s_shift[tid] = __ldg(&beta[tid]) - m * sc;
    }
    __syncthreads();
    int i = blockIdx.x * 256 + tid;
    int c4 = i & 31;
    float4 v  = *((const float4*)g_z0 + i);
    float4 sc = *(const float4*)(s_scale + c4 * 4);
    float4 sh = *(const float4*)(s_shift + c4 * 4);
    v.x = fmaf(v.x, sc.x, sh.x);
    v.y = fmaf(v.y, sc.y, sh.y);
    v.z = fmaf(v.z, sc.z, sh.z);
    v.w = fmaf(v.w, sc.w, sh.w);
    if (do_relu) {
        v.x = fmaxf(v.x, 0.f); v.y = fmaxf(v.y, 0.f);
        v.z = fmaxf(v.z, 0.f); v.w = fmaxf(v.w, 0.f);
    }
    float4 hh = h4[i];
    hh.x += v.x; hh.y += v.y; hh.z += v.z; hh.w += v.w;
    h4[i] = hh;
    ((uint2*)g_hh)[i] = f2h4(hh);
}

// ---------------- launcher ----------------
extern "C" void kernel_launch(void* const* d_in, const int* in_sizes, int n_in,
                              void* d_out, int out_size) {
    const int*   x_ids = (const int*)d_in[0];
    const int*   ei    = (const int*)d_in[1];
    const int*   eattr = (const int*)d_in[2];
    const float* atom  = (const float*)d_in[3];
    const float* bond  = (const float*)d_in[4];
    const float* W1    = (const float*)d_in[5];
    const float* b1    = (const float*)d_in[6];
    const float* g1    = (const float*)d_in[7];
    const float* bt1   = (const float*)d_in[8];
    const float* W2    = (const float*)d_in[9];
    const float* b2    = (const float*)d_in[10];
    const float* eps   = (const float*)d_in[11];
    const float* gout  = (const float*)d_in[12];
    const float* bout  = (const float*)d_in[13];
    float* h = (float*)d_out;

    cudaFuncSetAttribute(gemm_kernel<false>, cudaFuncAttributeMaxDynamicSharedMemorySize, SMEM_GEMM);
    cudaFuncSetAttribute(gemm_kernel<true>,  cudaFuncAttributeMaxDynamicSharedMemorySize, SMEM_GEMM);

    embed_kernel<<<5640, 256>>>((float4*)h, x_ids, (const float4*)atom, W1, W2);    // 0
    scan_scatter_kernel<<<40, 1024>>>(ei, eattr);                                   // 1

    for (int l = 0; l < LL; l++) {
        agg_kernel<<<NN / 8, 256>>>((const float4*)h, bond, eps, l);                // 2 (l=0)
        gemm_kernel<false><<<296, 256, SMEM_GEMM>>>(l * 2 + 0, b1 + l * DD,
                                                    nullptr, nullptr, 0);           // 3 (l=0) <- profiled
        gemm_kernel<true><<<296, 256, SMEM_GEMM>>>(l * 2 + 1, b2 + l * DD,
                                                   g1 + l * DD, bt1 + l * DD, 1);
        residual_kernel<<<NN * 32 / 256, 256>>>((float4*)h, gout + l * DD,
                                                bout + l * DD, (l < LL - 1) ? 1 : 0);
    }
    (void)in_sizes; (void)n_in; (void)out_size;
}

// round 17
// speedup vs baseline: 1.1145x; 1.1145x over previous
#include <cuda_runtime.h>
#include <cuda_fp16.h>
#include <cstdint>

#define NN 40000
#define EE 640000
#define DD 128
#define LL 5
#define NTILES 625          // NN / 64 (64-row GEMM tiles, exact)

// ---------------- device scratch (static, no allocation) ----------------
__device__ float g_z0[NN * DD];   // agg output / gemm2 output
__device__ float g_y1[NN * DD];   // gemm1 output
__device__ __half g_hh[NN * DD];  // fp16 shadow of h (gather source)
__device__ int   g_rowptr[NN + 1];
__device__ int   g_cursor[NN];
__device__ int   g_packed[EE];    // (src<<5) | (attr*32)<<21, grouped by dst
__device__ int   g_bflag[40];
__device__ int   g_bpre[40];
__device__ int   g_bar;
__device__ int   g_ctr[2];        // work-stealing counters (gemm1, gemm2)
__device__ float g_sum1[DD], g_sq1[DD];   // stats of gemm1 output (BN1)
__device__ float g_sum2[DD], g_sq2[DD];   // stats of gemm2 output (BN2)
__device__ uint4 g_wt4[10 * 2048];        // fp16 weights, transposed [n][k]

// ---------------- helpers ----------------
__device__ __forceinline__ uint32_t smem_u32(const void* p) {
    uint32_t a;
    asm("{ .reg .u64 t; cvta.to.shared.u64 t, %1; cvt.u32.u64 %0, t; }" : "=r"(a) : "l"(p));
    return a;
}
__device__ __forceinline__ void ldsm4(uint32_t a, uint32_t& r0, uint32_t& r1,
                                      uint32_t& r2, uint32_t& r3) {
    asm volatile("ldmatrix.sync.aligned.m8n8.x4.shared.b16 {%0,%1,%2,%3}, [%4];"
                 : "=r"(r0), "=r"(r1), "=r"(r2), "=r"(r3) : "r"(a));
}
__device__ __forceinline__ void mma16816h(float* c, const uint32_t* a, uint32_t b0, uint32_t b1) {
    asm volatile(
        "mma.sync.aligned.m16n8k16.row.col.f32.f16.f16.f32 "
        "{%0,%1,%2,%3}, {%4,%5,%6,%7}, {%8,%9}, {%0,%1,%2,%3};"
        : "+f"(c[0]), "+f"(c[1]), "+f"(c[2]), "+f"(c[3])
        : "r"(a[0]), "r"(a[1]), "r"(a[2]), "r"(a[3]), "r"(b0), "r"(b1));
}
// fp16 hi/lo split of two floats
__device__ __forceinline__ void split2h(float a, float b, uint32_t& hi, uint32_t& lo) {
    __half ha = __float2half_rn(a), hb = __float2half_rn(b);
    float ra = a - __half2float(ha), rb = b - __half2float(hb);
    __half2 ph = __halves2half2(ha, hb);
    __half2 pl = __halves2half2(__float2half_rn(ra), __float2half_rn(rb));
    hi = *(uint32_t*)&ph;
    lo = *(uint32_t*)&pl;
}
__device__ __forceinline__ uint2 f2h4(float4 v) {
    __half2 lo = __floats2half2_rn(v.x, v.y);
    __half2 hi = __floats2half2_rn(v.z, v.w);
    uint2 r;
    r.x = *(unsigned*)&lo;
    r.y = *(unsigned*)&hi;
    return r;
}
// message = relu(h_src + bond) for a uint4 (8 halves)
__device__ __forceinline__ void msg4(uint4 r, uint4 e, __half2* m, __half2 z2) {
    m[0] = __hmax2(__hadd2(*(__half2*)&r.x, *(__half2*)&e.x), z2);
    m[1] = __hmax2(__hadd2(*(__half2*)&r.y, *(__half2*)&e.y), z2);
    m[2] = __hmax2(__hadd2(*(__half2*)&r.z, *(__half2*)&e.z), z2);
    m[3] = __hmax2(__hadd2(*(__half2*)&r.w, *(__half2*)&e.w), z2);
}
__device__ __forceinline__ void flushh(__half2 c0, __half2 c1, __half2 c2, __half2 c3,
                                       float2& a0, float2& a1, float2& a2, float2& a3) {
    float2 f0 = __half22float2(c0), f1 = __half22float2(c1);
    float2 f2 = __half22float2(c2), f3 = __half22float2(c3);
    a0.x += f0.x; a0.y += f0.y;
    a1.x += f1.x; a1.y += f1.y;
    a2.x += f2.x; a2.y += f2.y;
    a3.x += f3.x; a3.y += f3.y;
}

// ---------------- embed + wconv + per-replay zeroing + fp16 shadow ----------------
__global__ void embed_kernel(float4* __restrict__ h4,
                             const int* __restrict__ x_ids,
                             const float4* __restrict__ atom4,
                             const float* __restrict__ W1,
                             const float* __restrict__ W2) {
    int blk = blockIdx.x;
    if (blk < 5000) {
        int i = blk * 256 + threadIdx.x;
        if (i < NN) g_cursor[i] = 0;
        if (i < 40) { g_bflag[i] = 0; g_bpre[i] = 0; }
        if (i < 2) g_ctr[i] = 0;
        if (i == 42) g_bar = 0;
        int n = i >> 5, c = i & 31;
        float4 v = __ldg(&atom4[x_ids[n] * 32 + c]);
        h4[i] = v;
        ((uint2*)g_hh)[i] = f2h4(v);
    } else {
        int i = (blk - 5000) * 256 + threadIdx.x;   // 0..163839
        int which = i >> 14;
        int j = i & 16383;
        int n = j >> 7, k = j & 127;
        const float* W = ((which & 1) ? W2 : W1) + (which >> 1) * DD * DD;
        ((__half*)g_wt4)[i] = __float2half_rn(__ldg(&W[k * DD + n]));
    }
}

// ---------------- CSR build: hist + scan (lookback) + scatter, one kernel ----------------
__global__ void __launch_bounds__(1024) scan_scatter_kernel(const int* __restrict__ ei,
                                                            const int* __restrict__ eattr) {
    __shared__ int wsum[32];
    __shared__ int s_boff;
    int tid = threadIdx.x, lane = tid & 31, wid = tid >> 5;
    int b = blockIdx.x;

    for (int e = b * 16000 + tid; e < (b + 1) * 16000; e += 1024)
        atomicAdd(&g_cursor[ei[EE + e]], 1);
    __threadfence();
    __syncthreads();
    if (tid == 0) {
        atomicAdd(&g_bar, 1);
        while (((volatile int*)&g_bar)[0] < 40) { }
    }
    __syncthreads();

    int i = b * 1024 + tid;
    int v = (i < NN) ? g_cursor[i] : 0;
    int x = v;
    #pragma unroll
    for (int o = 1; o < 32; o <<= 1) { int t = __shfl_up_sync(~0u, x, o); if (lane >= o) x += t; }
    if (lane == 31) wsum[wid] = x;
    __syncthreads();
    if (wid == 0) {
        int y = wsum[lane];
        #pragma unroll
        for (int o = 1; o < 32; o <<= 1) { int t = __shfl_up_sync(~0u, y, o); if (lane >= o) y += t; }
        wsum[lane] = y;
    }
    __syncthreads();
    int incl = (wid ? wsum[wid - 1] : 0) + x;
    if (tid == 0) {
        int total = wsum[31];
        int p = 0;
        if (b > 0) {
            while (((volatile int*)g_bflag)[b - 1] == 0) { }
            p = ((volatile int*)g_bpre)[b - 1];
        }
        g_bpre[b] = p + total;
        __threadfence();
        ((volatile int*)g_bflag)[b] = 1;
        s_boff = p;
    }
    __syncthreads();
    int boff = s_boff;
    if (i < NN) {
        g_rowptr[i + 1] = boff + incl;
        g_cursor[i] = boff + incl - v;
    }
    if (i == 0) g_rowptr[0] = 0;
    __threadfence();
    __syncthreads();
    if (tid == 0) {
        atomicAdd(&g_bar, 1);
        while (((volatile int*)&g_bar)[0] < 80) { }
    }
    __syncthreads();

    for (int e = b * 16000 + tid; e < (b + 1) * 16000; e += 1024) {
        int d = ei[EE + e];
        int p = atomicAdd(&g_cursor[d], 1);
        g_packed[p] = (ei[e] << 5) | ((eattr[e] << 5) << 21);
    }
}

// ---------------- edge aggregation (half-warp pairing) ----------------
__global__ void __launch_bounds__(256) agg_kernel(const float4* __restrict__ h4,
                                                  const float* __restrict__ bond_emb,
                                                  const float* __restrict__ eps, int l) {
    __shared__ uint4 sbe4[4 * 16];
    int tid = threadIdx.x;
    if (blockIdx.x == 0 && tid < 128) {
        g_sum1[tid] = 0.f; g_sq1[tid] = 0.f;
        g_sum2[tid] = 0.f; g_sq2[tid] = 0.f;
        if (tid < 2) g_ctr[tid] = 0;
    }
    if (tid < 64) {
        float4 a = __ldg((const float4*)(bond_emb + l * 512) + tid * 2);
        float4 b = __ldg((const float4*)(bond_emb + l * 512) + tid * 2 + 1);
        uint2 pa = f2h4(a), pb = f2h4(b);
        sbe4[tid] = make_uint4(pa.x, pa.y, pb.x, pb.y);
    }
    __syncthreads();
    int lane = tid & 31, hf = lane >> 4, li = lane & 15;
    int v = blockIdx.x * 8 + (tid >> 5);
    float ep = 1.0f + __ldg(&eps[l]);
    const uint4* hh4 = (const uint4*)g_hh;
    const __half2 z2 = __float2half2_rn(0.f);

    float2 a0, a1, a2, a3;
    if (hf == 0) {
        float4 h0 = __ldg(&h4[v * 32 + li * 2]);
        float4 h1 = __ldg(&h4[v * 32 + li * 2 + 1]);
        a0 = make_float2(h0.x * ep, h0.y * ep);
        a1 = make_float2(h0.z * ep, h0.w * ep);
        a2 = make_float2(h1.x * ep, h1.y * ep);
        a3 = make_float2(h1.z * ep, h1.w * ep);
    } else {
        a0 = a1 = a2 = a3 = make_float2(0.f, 0.f);
    }

    int start = g_rowptr[v], end = g_rowptr[v + 1];
    for (int base = start; base < end; base += 32) {
        int nl = min(32, end - base);
        int pk = (base + lane < end) ? g_packed[base + lane] : 0;
        for (int j = 0; j < nl; j += 4) {
            int eA = j + hf, eB = j + 2 + hf;
            int pA = __shfl_sync(~0u, pk, eA);
            int pB = __shfl_sync(~0u, pk, eB);
            bool vA = eA < nl, vB = eB < nl;
            uint4 rA = __ldg(&hh4[((pA & 0x1FFFFF) >> 1) + li]);
            uint4 eAv = sbe4[(((unsigned)pA >> 21) >> 1) + li];
            uint4 rB = __ldg(&hh4[((pB & 0x1FFFFF) >> 1) + li]);
            uint4 eBv = sbe4[(((unsigned)pB >> 21) >> 1) + li];
            __half2 mA[4], mB[4];
            msg4(rA, eAv, mA, z2);
            msg4(rB, eBv, mB, z2);
            if (vB) {
                flushh(__hadd2(mA[0], mB[0]), __hadd2(mA[1], mB[1]),
                       __hadd2(mA[2], mB[2]), __hadd2(mA[3], mB[3]), a0, a1, a2, a3);
            } else if (vA) {
                flushh(mA[0], mA[1], mA[2], mA[3], a0, a1, a2, a3);
            }
        }
    }
    a0.x += __shfl_xor_sync(~0u, a0.x, 16);
    a0.y += __shfl_xor_sync(~0u, a0.y, 16);
    a1.x += __shfl_xor_sync(~0u, a1.x, 16);
    a1.y += __shfl_xor_sync(~0u, a1.y, 16);
    a2.x += __shfl_xor_sync(~0u, a2.x, 16);
    a2.y += __shfl_xor_sync(~0u, a2.y, 16);
    a3.x += __shfl_xor_sync(~0u, a3.x, 16);
    a3.y += __shfl_xor_sync(~0u, a3.y, 16);
    if (hf == 0) {
        *((float4*)g_z0 + v * 32 + li * 2)     = make_float4(a0.x, a0.y, a1.x, a1.y);
        *((float4*)g_z0 + v * 32 + li * 2 + 1) = make_float4(a2.x, a2.y, a3.x, a3.y);
    }
}

// ---------------- tensor-core GEMM (mma.sync fp16, A hi/lo split, W fp16) ----------------
// CTA tile 64x128, 8 warps 2m x 4n, warp tile m32 x n32; 272-byte row stride.
// smem 71.7 KB -> 3 CTAs/SM (24 warps/SM).
#define SM_AH    0
#define SM_AL    17408
#define SM_B     34816
#define SM_SUM   69632
#define SM_SQ    70144
#define SM_SCALE 70656
#define SM_SHIFT 71168
#define SM_TILE  71680
#define SMEM_GEMM 71696

template <bool TRANS>
__global__ void __launch_bounds__(256, 3) gemm_kernel(int which,
                                                      const float* __restrict__ bias,
                                                      const float* __restrict__ gamma,
                                                      const float* __restrict__ beta,
                                                      int ctr_idx) {
    extern __shared__ char smem[];
    uint32_t sb = smem_u32(smem);
    float* s_sum   = (float*)(smem + SM_SUM);
    float* s_sq    = (float*)(smem + SM_SQ);
    float* s_scale = (float*)(smem + SM_SCALE);
    float* s_shift = (float*)(smem + SM_SHIFT);
    int*   s_tile  = (int*)(smem + SM_TILE);
    const float* A = TRANS ? g_y1 : g_z0;
    float* C       = TRANS ? g_z0 : g_y1;

    int tid = threadIdx.x, lane = tid & 31, wid = tid >> 5;
    if (tid < 128) {
        s_sum[tid] = 0.f; s_sq[tid] = 0.f;
        if (TRANS) {
            const float invN = 1.0f / (float)NN;
            float m   = g_sum1[tid] * invN;
            float var = g_sq1[tid] * invN - m * m;
            float sc  = __ldg(&gamma[tid]) * rsqrtf(var + 1e-5f);
            s_scale[tid] = sc;
            s_shift[tid] = __ldg(&beta[tid]) - m * sc;
        }
    }
    {   // stage W (fp16, [n][k] -> padded smem), once per CTA
        const uint4* src = g_wt4 + which * 2048;
        #pragma unroll
        for (int it = 0; it < 8; it++) {
            int s = it * 256 + tid;
            int row = s >> 4, ch = s & 15;
            *(uint4*)(smem + SM_B + row * 272 + ch * 16) = __ldg(&src[row * 16 + ch]);
        }
    }

    int mrow = (wid & 1) * 32;
    int ncol = (wid >> 1) * 32;
    int gm = lane & 7, gh = (lane >> 3) & 1, gk = lane >> 4;
    uint32_t aA0 = sb + (mrow + gm + gh * 8) * 272 + gk * 16;
    uint32_t aB0 = sb + (ncol + gm + gh * 8) * 272 + gk * 16;
    int ar = tid >> 5, ac4 = tid & 31;

    float st_sx0[4] = {}, st_sx1[4] = {}, st_sq0[4] = {}, st_sq1[4] = {};

    for (;;) {
        if (tid == 0) *s_tile = atomicAdd(&g_ctr[ctr_idx], 1);
        __syncthreads();
        int t = *s_tile;
        if (t >= NTILES) break;
        int rowblk = t * 64;

        {   // stage A tile (64 rows x 128), optional BN1+relu, fp16 hi/lo split
            float4 sc, sh;
            if (TRANS) {
                sc = *(const float4*)(s_scale + ac4 * 4);
                sh = *(const float4*)(s_shift + ac4 * 4);
            }
            #pragma unroll
            for (int i = 0; i < 8; i++) {
                int rr = ar + i * 8;
                float4 v = __ldg((const float4*)(A + (rowblk + rr) * DD) + ac4);
                if (TRANS) {
                    v.x = fmaxf(fmaf(v.x, sc.x, sh.x), 0.f);
                    v.y = fmaxf(fmaf(v.y, sc.y, sh.y), 0.f);
                    v.z = fmaxf(fmaf(v.z, sc.z, sh.z), 0.f);
                    v.w = fmaxf(fmaf(v.w, sc.w, sh.w), 0.f);
                }
                uint32_t h0, l0, h1, l1;
                split2h(v.x, v.y, h0, l0);
                split2h(v.z, v.w, h1, l1);
                char* p = smem + rr * 272 + ac4 * 8;
                *(uint2*)(p + SM_AH) = make_uint2(h0, h1);
                *(uint2*)(p + SM_AL) = make_uint2(l0, l1);
            }
        }
        __syncthreads();

        float c[2][4][4];
        #pragma unroll
        for (int mb = 0; mb < 2; mb++)
            #pragma unroll
            for (int i = 0; i < 4; i++)
                #pragma unroll
                for (int j = 0; j < 4; j++) c[mb][i][j] = 0.f;

        #pragma unroll
        for (int ks = 0; ks < 8; ks++) {
            uint32_t off = ks * 32;
            uint32_t ah[8], al[8], bb[8];
            ldsm4(aA0 + SM_AH + off,            ah[0], ah[1], ah[2], ah[3]);
            ldsm4(aA0 + SM_AH + 16 * 272 + off, ah[4], ah[5], ah[6], ah[7]);
            ldsm4(aA0 + SM_AL + off,            al[0], al[1], al[2], al[3]);
            ldsm4(aA0 + SM_AL + 16 * 272 + off, al[4], al[5], al[6], al[7]);
            ldsm4(aB0 + SM_B + off,             bb[0], bb[1], bb[2], bb[3]);
            ldsm4(aB0 + SM_B + 16 * 272 + off,  bb[4], bb[5], bb[6], bb[7]);
            #pragma unroll
            for (int mb = 0; mb < 2; mb++) {
                #pragma unroll
                for (int ng = 0; ng < 4; ng++) {
                    int bi = (ng >> 1) * 4 + (ng & 1);
                    mma16816h(c[mb][ng], ah + mb * 4, bb[bi], bb[bi + 2]);
                    mma16816h(c[mb][ng], al + mb * 4, bb[bi], bb[bi + 2]);
                }
            }
        }

        // epilogue: bias, store C; stats into registers only
        #pragma unroll
        for (int ng = 0; ng < 4; ng++) {
            int col0 = ncol + ng * 8 + 2 * (lane & 3);
            float bx = __ldg(&bias[col0]), by = __ldg(&bias[col0 + 1]);
            #pragma unroll
            for (int mb = 0; mb < 2; mb++) {
                int r0g = rowblk + mrow + mb * 16 + (lane >> 2);
                float x0 = c[mb][ng][0] + bx, x1 = c[mb][ng][1] + by;
                float x2 = c[mb][ng][2] + bx, x3 = c[mb][ng][3] + by;
                *(float2*)(C + r0g * DD + col0)       = make_float2(x0, x1);
                *(float2*)(C + (r0g + 8) * DD + col0) = make_float2(x2, x3);
                st_sx0[ng] += x0 + x2; st_sq0[ng] += x0 * x0 + x2 * x2;
                st_sx1[ng] += x1 + x3; st_sq1[ng] += x1 * x1 + x3 * x3;
            }
        }
        __syncthreads();
    }

    // final stats reduction (once per kernel)
    #pragma unroll
    for (int ng = 0; ng < 4; ng++) {
        float sx0 = st_sx0[ng], sq0 = st_sq0[ng], sx1 = st_sx1[ng], sq1 = st_sq1[ng];
        #pragma unroll
        for (int d = 4; d < 32; d <<= 1) {
            sx0 += __shfl_xor_sync(~0u, sx0, d);
            sq0 += __shfl_xor_sync(~0u, sq0, d);
            sx1 += __shfl_xor_sync(~0u, sx1, d);
            sq1 += __shfl_xor_sync(~0u, sq1, d);
        }
        if ((lane >> 2) == 0) {
            int col0 = ncol + ng * 8 + 2 * (lane & 3);
            atomicAdd(&s_sum[col0], sx0);
            atomicAdd(&s_sum[col0 + 1], sx1);
            atomicAdd(&s_sq[col0], sq0);
            atomicAdd(&s_sq[col0 + 1], sq1);
        }
    }
    __syncthreads();
    if (tid < 128) {
        if (TRANS) {
            atomicAdd(&g_sum2[tid], s_sum[tid]);
            atomicAdd(&g_sq2[tid],  s_sq[tid]);
        } else {
            atomicAdd(&g_sum1[tid], s_sum[tid]);
            atomicAdd(&g_sq1[tid],  s_sq[tid]);
        }
    }
}

// ---------------- BN2 + (relu) + residual + fp16 shadow refresh ----------------
__global__ void residual_kernel(float4* __restrict__ h4,
                                const float* __restrict__ gamma,
                                const float* __restrict__ beta,
                                int do_relu) {
    __shared__ float s_scale[128], s_shift[128];
    int tid = threadIdx.x;
    if (tid < 128) {
        const float invN = 1.0f / (float)NN;
        float m   = g_sum2[tid] * invN;
        float var = g_sq2[tid] * invN - m * m;
        float sc  = __ldg(&gamma[tid]) * rsqrtf(var + 1e-5f);
        s_scale[tid] = sc;
        s_shift[tid] = __ldg(&beta[tid]) - m * sc;
    }
    __syncthreads();
    int i = blockIdx.x * 256 + tid;
    int c4 = i & 31;
    float4 v  = *((const float4*)g_z0 + i);
    float4 sc = *(const float4*)(s_scale + c4 * 4);
    float4 sh = *(const float4*)(s_shift + c4 * 4);
    v.x = fmaf(v.x, sc.x, sh.x);
    v.y = fmaf(v.y, sc.y, sh.y);
    v.z = fmaf(v.z, sc.z, sh.z);
    v.w = fmaf(v.w, sc.w, sh.w);
    if (do_relu) {
        v.x = fmaxf(v.x, 0.f); v.y = fmaxf(v.y, 0.f);
        v.z = fmaxf(v.z, 0.f); v.w = fmaxf(v.w, 0.f);
    }
    float4 hh = h4[i];
    hh.x += v.x; hh.y += v.y; hh.z += v.z; hh.w += v.w;
    h4[i] = hh;
    ((uint2*)g_hh)[i] = f2h4(hh);
}

// ---------------- launcher ----------------
extern "C" void kernel_launch(void* const* d_in, const int* in_sizes, int n_in,
                              void* d_out, int out_size) {
    const int*   x_ids = (const int*)d_in[0];
    const int*   ei    = (const int*)d_in[1];
    const int*   eattr = (const int*)d_in[2];
    const float* atom  = (const float*)d_in[3];
    const float* bond  = (const float*)d_in[4];
    const float* W1    = (const float*)d_in[5];
    const float* b1    = (const float*)d_in[6];
    const float* g1    = (const float*)d_in[7];
    const float* bt1   = (const float*)d_in[8];
    const float* W2    = (const float*)d_in[9];
    const float* b2    = (const float*)d_in[10];
    const float* eps   = (const float*)d_in[11];
    const float* gout  = (const float*)d_in[12];
    const float* bout  = (const float*)d_in[13];
    float* h = (float*)d_out;

    cudaFuncSetAttribute(gemm_kernel<false>, cudaFuncAttributeMaxDynamicSharedMemorySize, SMEM_GEMM);
    cudaFuncSetAttribute(gemm_kernel<true>,  cudaFuncAttributeMaxDynamicSharedMemorySize, SMEM_GEMM);

    embed_kernel<<<5640, 256>>>((float4*)h, x_ids, (const float4*)atom, W1, W2);    // 0
    scan_scatter_kernel<<<40, 1024>>>(ei, eattr);                                   // 1

    for (int l = 0; l < LL; l++) {
        agg_kernel<<<NN / 8, 256>>>((const float4*)h, bond, eps, l);                // 2 (l=0)
        gemm_kernel<false><<<296, 256, SMEM_GEMM>>>(l * 2 + 0, b1 + l * DD,
                                                    nullptr, nullptr, 0);           // 3 (l=0) <- profiled
        gemm_kernel<true><<<296, 256, SMEM_GEMM>>>(l * 2 + 1, b2 + l * DD,
                                                   g1 + l * DD, bt1 + l * DD, 1);
        residual_kernel<<<NN * 32 / 256, 256>>>((float4*)h, gout + l * DD,
                                                bout + l * DD, (l < LL - 1) ? 1 : 0);
    }
    (void)in_sizes; (void)n_in; (void)out_size;
}